// round 3
// baseline (speedup 1.0000x reference)
#include <cuda_runtime.h>

#define NUM_BINS 20
#define NWARPS 8
#define THREADS 256
#define NBLOCKS 740   // 148 SMs * 5 CTAs (smem-limited), single wave
#define KBATCH 2

// Per-block partials, TRANSPOSED [bin][block] so the last-block reduction
// reads coalesced. No zero-init needed: every slot written every launch.
__device__ float2 g_part[NUM_BINS * NBLOCKS];
__device__ unsigned g_done;   // zero-initialized at module load; reset by last block

__global__ __launch_bounds__(THREADS, 5) void dwmse_fused_kernel(
    const float4* __restrict__ pred,
    const float4* __restrict__ target,
    int n4, float* __restrict__ out, int n)
{
    // Lane-private sub-histograms: [warp][bin][lane] float2{sum_sq_err, count}.
    // Each lane owns its column -> plain LDS.64/FADD/STS.64 RMW, no atomics,
    // no bank conflicts (8B lane stride = 128B per half-warp phase).
    __shared__ float2 s_acc[NWARPS * NUM_BINS * 32];
    __shared__ float2 s_red[NUM_BINS * NWARPS];
    __shared__ bool s_is_last;

    const int lane = threadIdx.x & 31;
    const int warp = threadIdx.x >> 5;
    float2* my = s_acc + warp * (NUM_BINS * 32) + lane;

    for (int i = threadIdx.x; i < NWARPS * NUM_BINS * 32; i += THREADS)
        s_acc[i] = make_float2(0.0f, 0.0f);
    __syncthreads();

    const int stride = gridDim.x * THREADS * KBATCH;
    for (int base = blockIdx.x * THREADS * KBATCH + threadIdx.x;
         base < n4; base += stride) {
        float4 p[KBATCH], t[KBATCH];
        bool valid[KBATCH];
        #pragma unroll
        for (int k = 0; k < KBATCH; k++) {       // front-batched: 4 LDG.128 in flight
            int idx = base + k * THREADS;
            valid[k] = idx < n4;
            if (valid[k]) {
                p[k] = __ldg(&pred[idx]);
                t[k] = __ldg(&target[idx]);
            }
        }
        #pragma unroll
        for (int k = 0; k < KBATCH; k++) {
            if (!valid[k]) continue;
            float d0 = p[k].x - t[k].x, d1 = p[k].y - t[k].y;
            float d2 = p[k].z - t[k].z, d3 = p[k].w - t[k].w;
            float se0 = d0 * d0, se1 = d1 * d1, se2 = d2 * d2, se3 = d3 * d3;
            // target in [0,1): trunc == floor, only upper clamp needed
            int b0 = min((int)(t[k].x * 20.0f), NUM_BINS - 1);
            int b1 = min((int)(t[k].y * 20.0f), NUM_BINS - 1);
            int b2 = min((int)(t[k].z * 20.0f), NUM_BINS - 1);
            int b3 = min((int)(t[k].w * 20.0f), NUM_BINS - 1);
            float2 c;
            c = my[b0 * 32]; c.x += se0; c.y += 1.0f; my[b0 * 32] = c;
            c = my[b1 * 32]; c.x += se1; c.y += 1.0f; my[b1 * 32] = c;
            c = my[b2 * 32]; c.x += se2; c.y += 1.0f; my[b2 * 32] = c;
            c = my[b3 * 32]; c.x += se3; c.y += 1.0f; my[b3 * 32] = c;
        }
    }
    __syncthreads();

    // Stage 1: 160 threads, one (bin,warp) column of 32 lanes each.
    if (threadIdx.x < NUM_BINS * NWARPS) {
        int b = threadIdx.x / NWARPS;
        int w = threadIdx.x % NWARPS;
        const float2* cell = s_acc + w * (NUM_BINS * 32) + b * 32;
        float s = 0.0f, cnt = 0.0f;
        #pragma unroll
        for (int l = 0; l < 32; l++) {
            float2 v = cell[l];
            s += v.x; cnt += v.y;
        }
        s_red[b * NWARPS + w] = make_float2(s, cnt);
    }
    __syncthreads();

    // Stage 2: 20 threads, write transposed global partial.
    if (threadIdx.x < NUM_BINS) {
        int b = threadIdx.x;
        float s = 0.0f, cnt = 0.0f;
        #pragma unroll
        for (int w = 0; w < NWARPS; w++) {
            float2 v = s_red[b * NWARPS + w];
            s += v.x; cnt += v.y;
        }
        g_part[b * NBLOCKS + blockIdx.x] = make_float2(s, cnt);
    }

    // ── Last-block finalize (threadFenceReduction pattern) ──────────────
    __syncthreads();
    if (threadIdx.x == 0) {
        __threadfence();                        // partials visible before ticket
        unsigned old = atomicAdd(&g_done, 1u);
        s_is_last = (old == NBLOCKS - 1);
    }
    __syncthreads();
    if (!s_is_last) return;

    __shared__ float f_sum[NUM_BINS];
    __shared__ float f_cnt[NUM_BINS];
    __shared__ float f_w[NUM_BINS];

    // Warps round-robin over bins; coalesced L2-resident reads (__ldcg
    // bypasses this SM's L1, which never saw other blocks' writes).
    for (int b = warp; b < NUM_BINS; b += NWARPS) {
        float s = 0.0f, c = 0.0f;
        for (int i = lane; i < NBLOCKS; i += 32) {
            float2 v = __ldcg(&g_part[b * NBLOCKS + i]);
            s += v.x; c += v.y;   // counts integer-valued fp32 < 2^24: exact
        }
        #pragma unroll
        for (int o = 16; o; o >>= 1) {
            s += __shfl_xor_sync(0xFFFFFFFFu, s, o);
            c += __shfl_xor_sync(0xFFFFFFFFu, c, o);
        }
        if (lane == 0) { f_sum[b] = s; f_cnt[b] = c; }
    }
    __syncthreads();

    // 20 parallel float pows (MUFU lg2/ex2 path).
    if (threadIdx.x < NUM_BINS)
        f_w[threadIdx.x] = powf(fmaxf(f_cnt[threadIdx.x], 1.0f), -0.9f);
    __syncthreads();

    if (threadIdx.x == 0) {
        float tot = 0.0f;
        #pragma unroll
        for (int b = 0; b < NUM_BINS; b++) tot += f_w[b];
        float acc = 0.0f;
        #pragma unroll
        for (int b = 0; b < NUM_BINS; b++) {
            float wb = (tot > 0.0f) ? (f_w[b] / tot * (float)NUM_BINS) : f_w[b];
            wb = fmaxf(wb, 1.0f);
            acc += wb * f_sum[b];
        }
        *out = acc / (float)n;
        g_done = 0;               // reset for next graph replay (deterministic)
    }
}

extern "C" void kernel_launch(void* const* d_in, const int* in_sizes, int n_in,
                              void* d_out, int out_size) {
    const float* pred = (const float*)d_in[0];
    const float* target = (const float*)d_in[1];
    int n = in_sizes[0];
    int n4 = n / 4;   // n = 2^24

    dwmse_fused_kernel<<<NBLOCKS, THREADS>>>((const float4*)pred,
                                             (const float4*)target,
                                             n4, (float*)d_out, n);
}

// round 4
// speedup vs baseline: 1.0007x; 1.0007x over previous
#include <cuda_runtime.h>

#define NUM_BINS 20
#define NWARPS 8
#define THREADS 256
#define NBLOCKS 740   // 148 SMs * 5 CTAs (smem-limited), single wave

// Per-block partials, transposed [bin][block] for coalesced last-block reads.
// No zero-init needed: every slot written every launch.
__device__ float2 g_part[NUM_BINS * NBLOCKS];
__device__ unsigned g_done;   // zero at load; reset by last block each launch

__device__ __forceinline__ void process4(float2* my, float4 p, float4 t) {
    float d0 = p.x - t.x, d1 = p.y - t.y, d2 = p.z - t.z, d3 = p.w - t.w;
    float se0 = d0 * d0, se1 = d1 * d1, se2 = d2 * d2, se3 = d3 * d3;
    // target in [0,1): trunc == floor, only upper clamp needed
    int b0 = min((int)(t.x * 20.0f), NUM_BINS - 1);
    int b1 = min((int)(t.y * 20.0f), NUM_BINS - 1);
    int b2 = min((int)(t.z * 20.0f), NUM_BINS - 1);
    int b3 = min((int)(t.w * 20.0f), NUM_BINS - 1);
    float2 c;
    c = my[b0 * 32]; c.x += se0; c.y += 1.0f; my[b0 * 32] = c;
    c = my[b1 * 32]; c.x += se1; c.y += 1.0f; my[b1 * 32] = c;
    c = my[b2 * 32]; c.x += se2; c.y += 1.0f; my[b2 * 32] = c;
    c = my[b3 * 32]; c.x += se3; c.y += 1.0f; my[b3 * 32] = c;
}

__global__ __launch_bounds__(THREADS, 5) void dwmse_fused_kernel(
    const float4* __restrict__ pred,
    const float4* __restrict__ target,
    int n4, float* __restrict__ out, int n)
{
    // Lane-private sub-histograms: [warp][bin][lane] float2{sum_sq_err, count}.
    // Plain LDS.64/FADD/STS.64 RMW, no atomics; bank = (lane*8)/4 mod 32 is
    // bin-independent -> conflict-free per half-warp phase.
    __shared__ float2 s_acc[NWARPS * NUM_BINS * 32];
    __shared__ float2 s_red[NUM_BINS * NWARPS];
    __shared__ bool s_is_last;

    const int lane = threadIdx.x & 31;
    const int warp = threadIdx.x >> 5;
    float2* my = s_acc + warp * (NUM_BINS * 32) + lane;

    for (int i = threadIdx.x; i < NWARPS * NUM_BINS * 32; i += THREADS)
        s_acc[i] = make_float2(0.0f, 0.0f);
    __syncthreads();

    // ── Software-pipelined streaming loop ──────────────────────────────
    // Slot s covers idx = tid0 + s*stride. Loads for slot s issue BEFORE
    // processing slot s-1, so every warp keeps 2 LDG.128 in flight during
    // its smem phase (latency hiding -> DRAM saturation).
    const int tid0 = blockIdx.x * THREADS + threadIdx.x;
    const int stride = NBLOCKS * THREADS;          // 189,440 float4 per slot
    const int full = n4 / stride;                  // 22 full slots for n=2^24
    const int rem = n4 - full * stride;            // tail float4 count

    float4 pc, tc, pn, tn;
    if (full > 0) {
        pc = __ldcs(&pred[tid0]);
        tc = __ldcs(&target[tid0]);
    }
    for (int s = 1; s < full; s++) {
        int idx = tid0 + s * stride;
        pn = __ldcs(&pred[idx]);                   // prefetch slot s
        tn = __ldcs(&target[idx]);
        process4(my, pc, tc);                      // process slot s-1
        pc = pn; tc = tn;
    }
    bool tail = tid0 < rem;
    if (tail) {
        int idx = tid0 + full * stride;
        pn = __ldcs(&pred[idx]);
        tn = __ldcs(&target[idx]);
    }
    if (full > 0) process4(my, pc, tc);
    if (tail)     process4(my, pn, tn);
    __syncthreads();

    // ── Block reduction ────────────────────────────────────────────────
    // Stage 1: 160 threads, one (bin,warp) column of 32 lanes each.
    if (threadIdx.x < NUM_BINS * NWARPS) {
        int b = threadIdx.x / NWARPS;
        int w = threadIdx.x % NWARPS;
        const float2* cell = s_acc + w * (NUM_BINS * 32) + b * 32;
        float s = 0.0f, cnt = 0.0f;
        #pragma unroll
        for (int l = 0; l < 32; l++) {
            float2 v = cell[l];
            s += v.x; cnt += v.y;
        }
        s_red[b * NWARPS + w] = make_float2(s, cnt);
    }
    __syncthreads();

    // Stage 2: 20 threads write the transposed global partial.
    if (threadIdx.x < NUM_BINS) {
        int b = threadIdx.x;
        float s = 0.0f, cnt = 0.0f;
        #pragma unroll
        for (int w = 0; w < NWARPS; w++) {
            float2 v = s_red[b * NWARPS + w];
            s += v.x; cnt += v.y;
        }
        g_part[b * NBLOCKS + blockIdx.x] = make_float2(s, cnt);
    }

    // ── Last-block finalize (threadFenceReduction pattern) ─────────────
    __syncthreads();
    if (threadIdx.x == 0) {
        __threadfence();                           // partials before ticket
        unsigned old = atomicAdd(&g_done, 1u);
        s_is_last = (old == NBLOCKS - 1);
    }
    __syncthreads();
    if (!s_is_last) return;

    __shared__ float f_sum[NUM_BINS];
    __shared__ float f_cnt[NUM_BINS];
    __shared__ float f_w[NUM_BINS];

    for (int b = warp; b < NUM_BINS; b += NWARPS) {
        float s = 0.0f, c = 0.0f;
        for (int i = lane; i < NBLOCKS; i += 32) {
            float2 v = __ldcg(&g_part[b * NBLOCKS + i]);   // L2-resident
            s += v.x; c += v.y;    // counts integer fp32 < 2^24: exact
        }
        #pragma unroll
        for (int o = 16; o; o >>= 1) {
            s += __shfl_xor_sync(0xFFFFFFFFu, s, o);
            c += __shfl_xor_sync(0xFFFFFFFFu, c, o);
        }
        if (lane == 0) { f_sum[b] = s; f_cnt[b] = c; }
    }
    __syncthreads();

    if (threadIdx.x < NUM_BINS)
        f_w[threadIdx.x] = powf(fmaxf(f_cnt[threadIdx.x], 1.0f), -0.9f);
    __syncthreads();

    if (threadIdx.x == 0) {
        float tot = 0.0f;
        #pragma unroll
        for (int b = 0; b < NUM_BINS; b++) tot += f_w[b];
        float acc = 0.0f;
        #pragma unroll
        for (int b = 0; b < NUM_BINS; b++) {
            float wb = (tot > 0.0f) ? (f_w[b] / tot * (float)NUM_BINS) : f_w[b];
            wb = fmaxf(wb, 1.0f);
            acc += wb * f_sum[b];
        }
        *out = acc / (float)n;
        g_done = 0;   // reset for next graph replay
    }
}

extern "C" void kernel_launch(void* const* d_in, const int* in_sizes, int n_in,
                              void* d_out, int out_size) {
    const float* pred = (const float*)d_in[0];
    const float* target = (const float*)d_in[1];
    int n = in_sizes[0];
    int n4 = n / 4;   // n = 2^24

    dwmse_fused_kernel<<<NBLOCKS, THREADS>>>((const float4*)pred,
                                             (const float4*)target,
                                             n4, (float*)d_out, n);
}